// round 1
// baseline (speedup 1.0000x reference)
#include <cuda_runtime.h>

#define T_ 256
#define B_ 128
#define I_ 512
#define H_ 1024
#define KS 4           // K-split for recurrence GEMM
#define KC (H_ / KS)   // 256

// Scratch (allocation-free rule: __device__ globals)
__device__ float g_xp[(size_t)T_ * B_ * H_];   // [T,B,H] input projection (+biases)
__device__ float g_h[B_ * H_];                 // current hidden state
__device__ float g_part[KS][B_ * H_];          // K-split partial sums

// ---------------------------------------------------------------------------
// Zero hidden state (must run every launch: graph replays must be deterministic)
// ---------------------------------------------------------------------------
__global__ void zero_h_kernel() {
    int i = blockIdx.x * blockDim.x + threadIdx.x;
    if (i < B_ * H_) g_h[i] = 0.0f;
}

// ---------------------------------------------------------------------------
// xp[m, n] = sum_i x[m, i] * W_ih[n, i] + b_ih[n] + b_hh[n]
// M = T*B = 32768, N = H = 1024, K = I = 512. Both operands K-contiguous.
// 128x128 tile, BK=8, 256 threads, 8x8 register micro-tile.
// ---------------------------------------------------------------------------
__global__ __launch_bounds__(256) void xp_gemm(const float* __restrict__ x,
                                               const float* __restrict__ Wih,
                                               const float* __restrict__ bih,
                                               const float* __restrict__ bhh) {
    __shared__ float As[8][128];
    __shared__ float Bs[8][128];
    int tid = threadIdx.x;
    int bx = blockIdx.x;   // n tile (0..7)
    int by = blockIdx.y;   // m tile (0..255)
    int ty = tid >> 4;     // 0..15 -> rows ty*8..ty*8+7
    int tx = tid & 15;     // 0..15 -> cols tx*8..tx*8+7

    float acc[8][8];
    #pragma unroll
    for (int i = 0; i < 8; i++)
        #pragma unroll
        for (int j = 0; j < 8; j++) acc[i][j] = 0.0f;

    int lrow = tid >> 1;          // 0..127
    int lkq  = (tid & 1) * 4;     // 0 or 4
    const float* xA = x   + (size_t)(by * 128 + lrow) * I_;
    const float* wB = Wih + (size_t)(bx * 128 + lrow) * I_;

    for (int k0 = 0; k0 < I_; k0 += 8) {
        float4 va = *(const float4*)(xA + k0 + lkq);
        float4 vb = *(const float4*)(wB + k0 + lkq);
        As[lkq + 0][lrow] = va.x; As[lkq + 1][lrow] = va.y;
        As[lkq + 2][lrow] = va.z; As[lkq + 3][lrow] = va.w;
        Bs[lkq + 0][lrow] = vb.x; Bs[lkq + 1][lrow] = vb.y;
        Bs[lkq + 2][lrow] = vb.z; Bs[lkq + 3][lrow] = vb.w;
        __syncthreads();

        #pragma unroll
        for (int k = 0; k < 8; k++) {
            // a: all lanes in half-warp share ty -> broadcast; b: float4 reads
            float4 a0 = *(const float4*)(&As[k][ty * 8]);
            float4 a1 = *(const float4*)(&As[k][ty * 8 + 4]);
            float4 b0 = *(const float4*)(&Bs[k][tx * 8]);
            float4 b1 = *(const float4*)(&Bs[k][tx * 8 + 4]);
            float a[8] = {a0.x, a0.y, a0.z, a0.w, a1.x, a1.y, a1.z, a1.w};
            float b[8] = {b0.x, b0.y, b0.z, b0.w, b1.x, b1.y, b1.z, b1.w};
            #pragma unroll
            for (int i = 0; i < 8; i++)
                #pragma unroll
                for (int j = 0; j < 8; j++)
                    acc[i][j] += a[i] * b[j];
        }
        __syncthreads();
    }

    #pragma unroll
    for (int i = 0; i < 8; i++) {
        int m = by * 128 + ty * 8 + i;
        #pragma unroll
        for (int j = 0; j < 8; j++) {
            int n = bx * 128 + tx * 8 + j;
            g_xp[(size_t)m * H_ + n] = acc[i][j] + bih[n] + bhh[n];
        }
    }
}

// ---------------------------------------------------------------------------
// Recurrence GEMM partial: g_part[s][b, j] = sum_{k in chunk s} h[b,k]*W_hh[j,k]
// Tile: 128 (all batches) x 32 j-cols, K chunk = 256 (BK=32).
// Grid: (32 j-tiles, KS k-chunks) = 128 CTAs. 256 threads, 8x2 micro-tile.
// ---------------------------------------------------------------------------
__global__ __launch_bounds__(256) void step_gemm(const float* __restrict__ Whh) {
    __shared__ float As[32][128];  // [k][b]
    __shared__ float Bs[32][32];   // [k][j]
    int tid = threadIdx.x;
    int J0 = blockIdx.x * 32;
    int s  = blockIdx.y;
    int k0 = s * KC;

    int tidm = tid >> 4;   // 0..15 -> batch rows tidm*8..+7 (broadcast in half-warp)
    int tidn = tid & 15;   // 0..15 -> cols tidn*2, tidn*2+1 (stride-2, conflict-free)

    float acc[8][2];
    #pragma unroll
    for (int i = 0; i < 8; i++) { acc[i][0] = 0.0f; acc[i][1] = 0.0f; }

    int brow = tid >> 3;          // 0..31
    int bkq  = (tid & 7) * 4;     // 0..28

    for (int kt = 0; kt < KC; kt += 32) {
        // load A (h): 128x32 = 1024 float4-lanes -> 4 float4 per thread
        #pragma unroll
        for (int f = 0; f < 4; f++) {
            int idx = tid + f * 256;
            int row = idx >> 3;
            int kq  = (idx & 7) * 4;
            float4 v = *(const float4*)(&g_h[row * H_ + k0 + kt + kq]);
            As[kq + 0][row] = v.x; As[kq + 1][row] = v.y;
            As[kq + 2][row] = v.z; As[kq + 3][row] = v.w;
        }
        // load B (W_hh rows J0..J0+31): 32x32 floats -> 1 float4 per thread
        {
            float4 v = *(const float4*)(&Whh[(size_t)(J0 + brow) * H_ + k0 + kt + bkq]);
            Bs[bkq + 0][brow] = v.x; Bs[bkq + 1][brow] = v.y;
            Bs[bkq + 2][brow] = v.z; Bs[bkq + 3][brow] = v.w;
        }
        __syncthreads();

        #pragma unroll
        for (int k = 0; k < 32; k++) {
            float4 a0 = *(const float4*)(&As[k][tidm * 8]);
            float4 a1 = *(const float4*)(&As[k][tidm * 8 + 4]);
            float a[8] = {a0.x, a0.y, a0.z, a0.w, a1.x, a1.y, a1.z, a1.w};
            float b0 = Bs[k][tidn * 2];
            float b1 = Bs[k][tidn * 2 + 1];
            #pragma unroll
            for (int i = 0; i < 8; i++) {
                acc[i][0] += a[i] * b0;
                acc[i][1] += a[i] * b1;
            }
        }
        __syncthreads();
    }

    #pragma unroll
    for (int i = 0; i < 8; i++) {
        int b = tidm * 8 + i;
        g_part[s][b * H_ + J0 + tidn * 2]     = acc[i][0];
        g_part[s][b * H_ + J0 + tidn * 2 + 1] = acc[i][1];
    }
}

// ---------------------------------------------------------------------------
// Reduce K-split partials + xp, tanh, write h, and fused W_fc head.
// One CTA per batch row, 256 threads x 4 elements (float4).
// ---------------------------------------------------------------------------
__global__ __launch_bounds__(256) void step_tanh_out(const float* __restrict__ Wfc,
                                                     const float* __restrict__ bfc,
                                                     float* __restrict__ out, int t) {
    __shared__ float red[256];
    int b = blockIdx.x;
    int tid = threadIdx.x;

    float4 p0 = ((const float4*)&g_part[0][b * H_])[tid];
    float4 p1 = ((const float4*)&g_part[1][b * H_])[tid];
    float4 p2 = ((const float4*)&g_part[2][b * H_])[tid];
    float4 p3 = ((const float4*)&g_part[3][b * H_])[tid];
    float4 xv = ((const float4*)&g_xp[((size_t)t * B_ + b) * H_])[tid];

    float h0 = tanhf(xv.x + p0.x + p1.x + p2.x + p3.x);
    float h1 = tanhf(xv.y + p0.y + p1.y + p2.y + p3.y);
    float h2 = tanhf(xv.z + p0.z + p1.z + p2.z + p3.z);
    float h3 = tanhf(xv.w + p0.w + p1.w + p2.w + p3.w);

    ((float4*)&g_h[b * H_])[tid] = make_float4(h0, h1, h2, h3);

    int j = tid * 4;
    float dot = h0 * Wfc[j] + h1 * Wfc[j + 1] + h2 * Wfc[j + 2] + h3 * Wfc[j + 3];
    red[tid] = dot;
    __syncthreads();
    #pragma unroll
    for (int s2 = 128; s2 > 0; s2 >>= 1) {
        if (tid < s2) red[tid] += red[tid + s2];
        __syncthreads();
    }
    if (tid == 0) out[t * B_ + b] = red[0] + bfc[0];
}

// ---------------------------------------------------------------------------
extern "C" void kernel_launch(void* const* d_in, const int* in_sizes, int n_in,
                              void* d_out, int out_size) {
    const float* x   = (const float*)d_in[0];
    const float* Wih = (const float*)d_in[1];
    const float* Whh = (const float*)d_in[2];
    const float* bih = (const float*)d_in[3];
    const float* bhh = (const float*)d_in[4];
    const float* Wfc = (const float*)d_in[5];
    const float* bfc = (const float*)d_in[6];
    float* out = (float*)d_out;

    zero_h_kernel<<<(B_ * H_ + 255) / 256, 256>>>();
    xp_gemm<<<dim3(8, 256), 256>>>(x, Wih, bih, bhh);
    for (int t = 0; t < T_; t++) {
        step_gemm<<<dim3(H_ / 32, KS), 256>>>(Whh);
        step_tanh_out<<<B_, 256>>>(Wfc, bfc, out, t);
    }
}

// round 2
// speedup vs baseline: 1.3645x; 1.3645x over previous
#include <cuda_runtime.h>

#define TT 256
#define BB 128
#define II 512
#define HH 1024
#define NJT 16        // j-tiles of 64 columns
#define NKS 8         // K-splits of 128
#define GRID_P (NJT * NKS)   // 128 persistent CTAs

// ---------------- scratch (allocation-free rule: __device__ globals) -------
__device__ float g_xp[(size_t)TT * BB * HH];     // [T,B,H] input projection (+biases)
__device__ float g_h[BB * HH];                   // hidden state (fp32)
__device__ float g_part[NKS][BB * HH];           // K-split partial sums
__device__ unsigned g_bar_count;
__device__ unsigned g_bar_gen;

// ---------------- tf32 helpers --------------------------------------------
__device__ __forceinline__ void tf32_split(float x, unsigned &hi, unsigned &lo) {
    asm("cvt.rna.tf32.f32 %0, %1;" : "=r"(hi) : "f"(x));
    float r = x - __uint_as_float(hi);
    asm("cvt.rna.tf32.f32 %0, %1;" : "=r"(lo) : "f"(r));
}

#define MMA_TF32(d, a, b)                                                       \
    asm volatile(                                                               \
        "mma.sync.aligned.m16n8k8.row.col.f32.tf32.tf32.f32 "                   \
        "{%0,%1,%2,%3},{%4,%5,%6,%7},{%8,%9},{%0,%1,%2,%3};\n"                  \
        : "+f"((d)[0]), "+f"((d)[1]), "+f"((d)[2]), "+f"((d)[3])                \
        : "r"((a)[0]), "r"((a)[1]), "r"((a)[2]), "r"((a)[3]),                   \
          "r"((b)[0]), "r"((b)[1]))

// ---------------- grid barrier (all CTAs co-resident: 128 <= 148 SMs) ------
__device__ __forceinline__ void grid_sync_() {
    __threadfence();
    __syncthreads();
    if (threadIdx.x == 0) {
        unsigned gen = *(volatile unsigned*)&g_bar_gen;
        if (atomicAdd(&g_bar_count, 1u) == gridDim.x - 1) {
            g_bar_count = 0;
            __threadfence();
            *(volatile unsigned*)&g_bar_gen = gen + 1;
        } else {
            while (*(volatile unsigned*)&g_bar_gen == gen) { }
        }
        __threadfence();
    }
    __syncthreads();
}

// ---------------- init: zero h + barrier state -----------------------------
__global__ void init_kernel() {
    int i = blockIdx.x * blockDim.x + threadIdx.x;
    if (i < BB * HH) g_h[i] = 0.0f;
    if (i == 0) { g_bar_count = 0; g_bar_gen = 0; }
}

// ---------------------------------------------------------------------------
// xp = x @ W_ih^T + b_ih + b_hh via 3xTF32 mma. M=T*B=32768, N=1024, K=512.
// CTA tile 128x128, 8 warps (2m x 4n), warp tile 64x32, BK=32.
// ---------------------------------------------------------------------------
__global__ __launch_bounds__(256) void xp_mma(const float* __restrict__ x,
                                              const float* __restrict__ Wih,
                                              const float* __restrict__ bih,
                                              const float* __restrict__ bhh) {
    extern __shared__ unsigned smx[];
    unsigned* Ash = smx;                 // [128][36]
    unsigned* Asl = Ash + 128 * 36;
    unsigned* Bsh = Asl + 128 * 36;
    unsigned* Bsl = Bsh + 128 * 36;      // total 4*128*36*4 = 73728 B

    int tid = threadIdx.x;
    int lane = tid & 31, w = tid >> 5;
    int g = lane >> 2, tg = lane & 3;
    int wm = (w & 1) * 64, wn = (w >> 1) * 32;
    int bn = blockIdx.x, bm = blockIdx.y;

    float acc[4][4][4];
    #pragma unroll
    for (int i = 0; i < 4; i++)
        #pragma unroll
        for (int j = 0; j < 4; j++)
            #pragma unroll
            for (int k = 0; k < 4; k++) acc[i][j][k] = 0.0f;

    int r = tid >> 1, koff = (tid & 1) * 16;
    const float* ax = x   + (size_t)(bm * 128 + r) * II;
    const float* bw = Wih + (size_t)(bn * 128 + r) * II;

    for (int kb = 0; kb < II; kb += 32) {
        #pragma unroll
        for (int i = 0; i < 4; i++) {
            float4 v = *(const float4*)(ax + kb + koff + 4 * i);
            unsigned h0, l0, h1, l1, h2, l2, h3, l3;
            tf32_split(v.x, h0, l0); tf32_split(v.y, h1, l1);
            tf32_split(v.z, h2, l2); tf32_split(v.w, h3, l3);
            unsigned* dh = Ash + r * 36 + koff + 4 * i;
            unsigned* dl = Asl + r * 36 + koff + 4 * i;
            dh[0] = h0; dh[1] = h1; dh[2] = h2; dh[3] = h3;
            dl[0] = l0; dl[1] = l1; dl[2] = l2; dl[3] = l3;

            float4 u = *(const float4*)(bw + kb + koff + 4 * i);
            tf32_split(u.x, h0, l0); tf32_split(u.y, h1, l1);
            tf32_split(u.z, h2, l2); tf32_split(u.w, h3, l3);
            dh = Bsh + r * 36 + koff + 4 * i;
            dl = Bsl + r * 36 + koff + 4 * i;
            dh[0] = h0; dh[1] = h1; dh[2] = h2; dh[3] = h3;
            dl[0] = l0; dl[1] = l1; dl[2] = l2; dl[3] = l3;
        }
        __syncthreads();

        #pragma unroll
        for (int ki = 0; ki < 4; ki++) {
            int k0 = ki * 8;
            unsigned ah[4][4], al[4][4], bh[4][2], bl[4][2];
            #pragma unroll
            for (int mi = 0; mi < 4; mi++) {
                int row = wm + 16 * mi + g;
                int base = row * 36 + k0 + tg;
                ah[mi][0] = Ash[base];            ah[mi][1] = Ash[base + 8 * 36];
                ah[mi][2] = Ash[base + 4];        ah[mi][3] = Ash[base + 8 * 36 + 4];
                al[mi][0] = Asl[base];            al[mi][1] = Asl[base + 8 * 36];
                al[mi][2] = Asl[base + 4];        al[mi][3] = Asl[base + 8 * 36 + 4];
            }
            #pragma unroll
            for (int ni = 0; ni < 4; ni++) {
                int n = wn + 8 * ni + g;
                int base = n * 36 + k0 + tg;
                bh[ni][0] = Bsh[base]; bh[ni][1] = Bsh[base + 4];
                bl[ni][0] = Bsl[base]; bl[ni][1] = Bsl[base + 4];
            }
            #pragma unroll
            for (int mi = 0; mi < 4; mi++)
                #pragma unroll
                for (int ni = 0; ni < 4; ni++) {
                    MMA_TF32(acc[mi][ni], ah[mi], bh[ni]);
                    MMA_TF32(acc[mi][ni], ah[mi], bl[ni]);
                    MMA_TF32(acc[mi][ni], al[mi], bh[ni]);
                }
        }
        __syncthreads();
    }

    #pragma unroll
    for (int mi = 0; mi < 4; mi++)
        #pragma unroll
        for (int ni = 0; ni < 4; ni++) {
            int m = bm * 128 + wm + 16 * mi + g;
            int n = bn * 128 + wn + 8 * ni + 2 * tg;
            float b0 = bih[n] + bhh[n];
            float b1 = bih[n + 1] + bhh[n + 1];
            float2 v0 = make_float2(acc[mi][ni][0] + b0, acc[mi][ni][1] + b1);
            float2 v1 = make_float2(acc[mi][ni][2] + b0, acc[mi][ni][3] + b1);
            *(float2*)(g_xp + (size_t)m * HH + n) = v0;
            *(float2*)(g_xp + (size_t)(m + 8) * HH + n) = v1;
        }
}

// ---------------------------------------------------------------------------
// Persistent recurrence: 128 CTAs = 16 j-tiles x 8 K-splits, 256 threads.
// W_hh slice (64 rows x 128 k, hi+lo tf32) lives in smem for all 256 steps.
// Per step: phase1 mma partials -> grid sync -> phase2 reduce+tanh+head -> sync.
// ---------------------------------------------------------------------------
__global__ __launch_bounds__(256, 1) void rnn_persistent(const float* __restrict__ Whh,
                                                         const float* __restrict__ Wfc,
                                                         const float* __restrict__ bfc,
                                                         float* __restrict__ out) {
    extern __shared__ unsigned smp[];
    unsigned* Bsh = smp;                  // [64][132]
    unsigned* Bsl = Bsh + 64 * 132;
    unsigned* Ash = Bsl + 64 * 132;       // [128][132]
    unsigned* Asl = Ash + 128 * 132;
    float*    red = (float*)(Asl + 128 * 132);   // [256]

    int tid = threadIdx.x;
    int bxid = blockIdx.x;
    int jt = bxid & (NJT - 1);
    int ks = bxid >> 4;
    int lane = tid & 31, w = tid >> 5;
    int g = lane >> 2, tg = lane & 3;
    int wm = (w & 3) * 32, wn = (w >> 2) * 32;

    // Load this CTA's W_hh slice once: rows jt*64..+63, k ks*128..+127
    {
        int n = tid >> 2;
        int koff = (tid & 3) * 32;
        const float* src = Whh + (size_t)(jt * 64 + n) * HH + ks * 128 + koff;
        unsigned* dh = Bsh + n * 132 + koff;
        unsigned* dl = Bsl + n * 132 + koff;
        #pragma unroll
        for (int i = 0; i < 8; i++) {
            float4 v = *(const float4*)(src + 4 * i);
            unsigned h0, l0, h1, l1, h2, l2, h3, l3;
            tf32_split(v.x, h0, l0); tf32_split(v.y, h1, l1);
            tf32_split(v.z, h2, l2); tf32_split(v.w, h3, l3);
            dh[4 * i + 0] = h0; dh[4 * i + 1] = h1; dh[4 * i + 2] = h2; dh[4 * i + 3] = h3;
            dl[4 * i + 0] = l0; dl[4 * i + 1] = l1; dl[4 * i + 2] = l2; dl[4 * i + 3] = l3;
        }
    }
    __syncthreads();

    int r = tid >> 1, koff = (tid & 1) * 64;

    for (int t = 0; t < TT; t++) {
        // ---- phase 1: stage h slice, split to tf32 hi/lo ----
        {
            const float* hsrc = g_h + r * HH + ks * 128 + koff;
            unsigned* dh = Ash + r * 132 + koff;
            unsigned* dl = Asl + r * 132 + koff;
            #pragma unroll
            for (int i = 0; i < 16; i++) {
                float4 v = *(const float4*)(hsrc + 4 * i);
                unsigned h0, l0, h1, l1, h2, l2, h3, l3;
                tf32_split(v.x, h0, l0); tf32_split(v.y, h1, l1);
                tf32_split(v.z, h2, l2); tf32_split(v.w, h3, l3);
                dh[4 * i + 0] = h0; dh[4 * i + 1] = h1; dh[4 * i + 2] = h2; dh[4 * i + 3] = h3;
                dl[4 * i + 0] = l0; dl[4 * i + 1] = l1; dl[4 * i + 2] = l2; dl[4 * i + 3] = l3;
            }
        }
        __syncthreads();

        float acc[2][4][4];
        #pragma unroll
        for (int i = 0; i < 2; i++)
            #pragma unroll
            for (int j = 0; j < 4; j++)
                #pragma unroll
                for (int k = 0; k < 4; k++) acc[i][j][k] = 0.0f;

        #pragma unroll
        for (int ki = 0; ki < 16; ki++) {
            int k0 = ki * 8;
            unsigned ah[2][4], al[2][4], bh[4][2], bl[4][2];
            #pragma unroll
            for (int mi = 0; mi < 2; mi++) {
                int row = wm + 16 * mi + g;
                int base = row * 132 + k0 + tg;
                ah[mi][0] = Ash[base];             ah[mi][1] = Ash[base + 8 * 132];
                ah[mi][2] = Ash[base + 4];         ah[mi][3] = Ash[base + 8 * 132 + 4];
                al[mi][0] = Asl[base];             al[mi][1] = Asl[base + 8 * 132];
                al[mi][2] = Asl[base + 4];         al[mi][3] = Asl[base + 8 * 132 + 4];
            }
            #pragma unroll
            for (int ni = 0; ni < 4; ni++) {
                int n = wn + 8 * ni + g;
                int base = n * 132 + k0 + tg;
                bh[ni][0] = Bsh[base]; bh[ni][1] = Bsh[base + 4];
                bl[ni][0] = Bsl[base]; bl[ni][1] = Bsl[base + 4];
            }
            #pragma unroll
            for (int mi = 0; mi < 2; mi++)
                #pragma unroll
                for (int ni = 0; ni < 4; ni++) {
                    MMA_TF32(acc[mi][ni], ah[mi], bh[ni]);
                    MMA_TF32(acc[mi][ni], ah[mi], bl[ni]);
                    MMA_TF32(acc[mi][ni], al[mi], bh[ni]);
                }
        }

        // write partials
        {
            float* pbase = g_part[ks];
            #pragma unroll
            for (int mi = 0; mi < 2; mi++)
                #pragma unroll
                for (int ni = 0; ni < 4; ni++) {
                    int row = wm + 16 * mi + g;
                    int col = jt * 64 + wn + 8 * ni + 2 * tg;
                    float2 v0 = make_float2(acc[mi][ni][0], acc[mi][ni][1]);
                    float2 v1 = make_float2(acc[mi][ni][2], acc[mi][ni][3]);
                    *(float2*)(pbase + row * HH + col) = v0;
                    *(float2*)(pbase + (row + 8) * HH + col) = v1;
                }
        }
        grid_sync_();

        // ---- phase 2: reduce partials + xp, tanh, write h, head dot ----
        {
            int b = bxid;  // 128 CTAs <-> 128 batches
            int j = tid * 4;
            float4 s = *(const float4*)(g_xp + ((size_t)t * BB + b) * HH + j);
            #pragma unroll
            for (int p = 0; p < NKS; p++) {
                float4 v = *(const float4*)(g_part[p] + b * HH + j);
                s.x += v.x; s.y += v.y; s.z += v.z; s.w += v.w;
            }
            float h0 = tanhf(s.x), h1 = tanhf(s.y), h2 = tanhf(s.z), h3 = tanhf(s.w);
            *(float4*)(g_h + b * HH + j) = make_float4(h0, h1, h2, h3);

            float4 wv = *(const float4*)(Wfc + j);
            red[tid] = h0 * wv.x + h1 * wv.y + h2 * wv.z + h3 * wv.w;
            __syncthreads();
            #pragma unroll
            for (int s2 = 128; s2 > 0; s2 >>= 1) {
                if (tid < s2) red[tid] += red[tid + s2];
                __syncthreads();
            }
            if (tid == 0) out[t * BB + b] = red[0] + bfc[0];
        }
        grid_sync_();
    }
}

// ---------------------------------------------------------------------------
extern "C" void kernel_launch(void* const* d_in, const int* in_sizes, int n_in,
                              void* d_out, int out_size) {
    const float* x   = (const float*)d_in[0];
    const float* Wih = (const float*)d_in[1];
    const float* Whh = (const float*)d_in[2];
    const float* bih = (const float*)d_in[3];
    const float* bhh = (const float*)d_in[4];
    const float* Wfc = (const float*)d_in[5];
    const float* bfc = (const float*)d_in[6];
    float* out = (float*)d_out;

    static int configured = 0;
    if (!configured) {
        cudaFuncSetAttribute(xp_mma, cudaFuncAttributeMaxDynamicSharedMemorySize, 73728);
        cudaFuncSetAttribute(rnn_persistent, cudaFuncAttributeMaxDynamicSharedMemorySize, 203776);
        configured = 1;
    }

    init_kernel<<<(BB * HH + 255) / 256, 256>>>();
    xp_mma<<<dim3(8, 256), 256, 73728>>>(x, Wih, bih, bhh);
    rnn_persistent<<<GRID_P, 256, 203776>>>(Whh, Wfc, bfc, out);
}

// round 7
// speedup vs baseline: 1.3801x; 1.0115x over previous
#include <cuda_runtime.h>
#include <cuda_bf16.h>

#define TT 256
#define BB 128
#define II 512
#define HH 1024
#define NJT 16
#define NKS 8
#define GRID_P (NJT * NKS)   // 128 persistent CTAs

#define AW 68   // smem row stride (words) persistent kernel
#define XW 20   // smem row stride (words) xp kernel

// ---------------- scratch ---------------------------------------------------
__device__ float g_xp[(size_t)TT * BB * HH];
__device__ unsigned g_hhi[BB * HH / 2];   // packed bf16x2 hidden (hi part)
__device__ unsigned g_hlo[BB * HH / 2];   // packed bf16x2 hidden (lo part)
__device__ float g_part[NKS][BB * HH];
__device__ unsigned g_flags[GRID_P * 32]; // one flag per 128B line
__device__ unsigned g_gen;

// ---------------- bf16 split helpers ---------------------------------------
__device__ __forceinline__ float bhi(float x) {
    unsigned u = __float_as_uint(x);
    u = (u + 0x7FFFu + ((u >> 16) & 1u)) & 0xFFFF0000u;
    return __uint_as_float(u);
}
// word = {lo16: bf16(e), hi16: bf16(o)}  (e = even k, o = odd k)
__device__ __forceinline__ void split_pair(float e, float o, unsigned &whi, unsigned &wlo) {
    float eh = bhi(e), oh = bhi(o);
    whi = (__float_as_uint(eh) >> 16) | (__float_as_uint(oh) & 0xFFFF0000u);
    float el = e - eh, ol = o - oh;
    asm("cvt.rn.bf16x2.f32 %0, %1, %2;" : "=r"(wlo) : "f"(ol), "f"(el));
}

#define MMA_BF16(d, a, b)                                                       \
    asm volatile(                                                               \
        "mma.sync.aligned.m16n8k16.row.col.f32.bf16.bf16.f32 "                  \
        "{%0,%1,%2,%3},{%4,%5,%6,%7},{%8,%9},{%0,%1,%2,%3};\n"                  \
        : "+f"((d)[0]), "+f"((d)[1]), "+f"((d)[2]), "+f"((d)[3])                \
        : "r"((a)[0]), "r"((a)[1]), "r"((a)[2]), "r"((a)[3]),                   \
          "r"((b)[0]), "r"((b)[1]))

// ---------------- barrier ---------------------------------------------------
__device__ __forceinline__ unsigned ld_acq(const unsigned* p) {
    unsigned v; asm volatile("ld.acquire.gpu.global.u32 %0, [%1];" : "=r"(v) : "l"(p)); return v;
}
__device__ __forceinline__ void st_rel(unsigned* p, unsigned v) {
    asm volatile("st.release.gpu.global.u32 [%0], %1;" :: "l"(p), "r"(v));
}
__device__ __forceinline__ void gsync(unsigned gen, int bxid, int tid) {
    __syncthreads();
    if (tid == 0) st_rel(&g_flags[bxid * 32], gen);
    if (bxid == 0) {
        if (tid < GRID_P) { while (ld_acq(&g_flags[tid * 32]) < gen) {} }
        __syncthreads();
        if (tid == 0) st_rel(&g_gen, gen);
    } else {
        if (tid == 0) { while (ld_acq(&g_gen) < gen) {} }
        __syncthreads();
    }
}

// ---------------- init ------------------------------------------------------
__global__ void init_kernel() {
    int i = blockIdx.x * blockDim.x + threadIdx.x;
    if (i < BB * HH / 2) { g_hhi[i] = 0u; g_hlo[i] = 0u; }
    if (i < GRID_P * 32) g_flags[i] = 0u;
    if (i == 0) g_gen = 0u;
}

// ---------------------------------------------------------------------------
// xp = x @ W_ih^T + b_ih + b_hh via bf16x3. M=32768, N=1024, K=512.
// CTA 128x128, 8 warps (2m x 4n): warp tile 64x32, BK=32.
// ---------------------------------------------------------------------------
__global__ __launch_bounds__(256) void xp_mma(const float* __restrict__ x,
                                              const float* __restrict__ Wih,
                                              const float* __restrict__ bih,
                                              const float* __restrict__ bhh) {
    __shared__ unsigned Ash[128 * XW], Asl[128 * XW];
    __shared__ unsigned Bsh[128 * XW], Bsl[128 * XW];

    int tid = threadIdx.x;
    int lane = tid & 31, w = tid >> 5;
    int g = lane >> 2, tg = lane & 3;
    int wm = (w & 1) * 64, wn = (w >> 1) * 32;
    int bn = blockIdx.x, bm = blockIdx.y;

    float acc[4][4][4];
    #pragma unroll
    for (int i = 0; i < 4; i++)
        #pragma unroll
        for (int j = 0; j < 4; j++)
            #pragma unroll
            for (int k = 0; k < 4; k++) acc[i][j][k] = 0.0f;

    int r = tid >> 1, half = tid & 1;
    const float* ax = x   + (size_t)(bm * 128 + r) * II + half * 16;
    const float* bw = Wih + (size_t)(bn * 128 + r) * II + half * 16;

    for (int kb = 0; kb < II; kb += 32) {
        unsigned hw[8], lw[8];
        #pragma unroll
        for (int i = 0; i < 4; i++) {
            float4 v = *(const float4*)(ax + kb + 4 * i);
            split_pair(v.x, v.y, hw[2 * i], lw[2 * i]);
            split_pair(v.z, v.w, hw[2 * i + 1], lw[2 * i + 1]);
        }
        {
            uint4* dh = (uint4*)&Ash[r * XW + half * 8];
            uint4* dl = (uint4*)&Asl[r * XW + half * 8];
            dh[0] = make_uint4(hw[0], hw[1], hw[2], hw[3]);
            dh[1] = make_uint4(hw[4], hw[5], hw[6], hw[7]);
            dl[0] = make_uint4(lw[0], lw[1], lw[2], lw[3]);
            dl[1] = make_uint4(lw[4], lw[5], lw[6], lw[7]);
        }
        #pragma unroll
        for (int i = 0; i < 4; i++) {
            float4 v = *(const float4*)(bw + kb + 4 * i);
            split_pair(v.x, v.y, hw[2 * i], lw[2 * i]);
            split_pair(v.z, v.w, hw[2 * i + 1], lw[2 * i + 1]);
        }
        {
            uint4* dh = (uint4*)&Bsh[r * XW + half * 8];
            uint4* dl = (uint4*)&Bsl[r * XW + half * 8];
            dh[0] = make_uint4(hw[0], hw[1], hw[2], hw[3]);
            dh[1] = make_uint4(hw[4], hw[5], hw[6], hw[7]);
            dl[0] = make_uint4(lw[0], lw[1], lw[2], lw[3]);
            dl[1] = make_uint4(lw[4], lw[5], lw[6], lw[7]);
        }
        __syncthreads();

        #pragma unroll
        for (int ki = 0; ki < 2; ki++) {
            int k0 = ki * 8;
            unsigned ah[4][4], al[4][4], bh[4][2], bl[4][2];
            #pragma unroll
            for (int mi = 0; mi < 4; mi++) {
                int base = (wm + 16 * mi + g) * XW + k0 + tg;
                ah[mi][0] = Ash[base];          ah[mi][1] = Ash[base + 8 * XW];
                ah[mi][2] = Ash[base + 4];      ah[mi][3] = Ash[base + 8 * XW + 4];
                al[mi][0] = Asl[base];          al[mi][1] = Asl[base + 8 * XW];
                al[mi][2] = Asl[base + 4];      al[mi][3] = Asl[base + 8 * XW + 4];
            }
            #pragma unroll
            for (int ni = 0; ni < 4; ni++) {
                int base = (wn + 8 * ni + g) * XW + k0 + tg;
                bh[ni][0] = Bsh[base]; bh[ni][1] = Bsh[base + 4];
                bl[ni][0] = Bsl[base]; bl[ni][1] = Bsl[base + 4];
            }
            #pragma unroll
            for (int mi = 0; mi < 4; mi++)
                #pragma unroll
                for (int ni = 0; ni < 4; ni++) {
                    MMA_BF16(acc[mi][ni], ah[mi], bh[ni]);
                    MMA_BF16(acc[mi][ni], ah[mi], bl[ni]);
                    MMA_BF16(acc[mi][ni], al[mi], bh[ni]);
                }
        }
        __syncthreads();
    }

    #pragma unroll
    for (int mi = 0; mi < 4; mi++)
        #pragma unroll
        for (int ni = 0; ni < 4; ni++) {
            int m = bm * 128 + wm + 16 * mi + g;
            int n = bn * 128 + wn + 8 * ni + 2 * tg;
            float b0 = bih[n] + bhh[n];
            float b1 = bih[n + 1] + bhh[n + 1];
            *(float2*)(g_xp + (size_t)m * HH + n) =
                make_float2(acc[mi][ni][0] + b0, acc[mi][ni][1] + b1);
            *(float2*)(g_xp + (size_t)(m + 8) * HH + n) =
                make_float2(acc[mi][ni][2] + b0, acc[mi][ni][3] + b1);
        }
}

// ---------------------------------------------------------------------------
// Persistent recurrence: 128 CTAs = 16 jt x 8 ks, 256 threads, bf16x3 mma.
// ---------------------------------------------------------------------------
__global__ __launch_bounds__(256, 1) void rnn_persistent(const float* __restrict__ Whh,
                                                         const float* __restrict__ Wfc,
                                                         const float* __restrict__ bfc,
                                                         float* __restrict__ out) {
    extern __shared__ unsigned sm[];
    unsigned* Bsh = sm;                 // [64][AW]
    unsigned* Bsl = Bsh + 64 * AW;
    unsigned* Ash = Bsl + 64 * AW;      // [128][AW]
    unsigned* Asl = Ash + 128 * AW;
    __shared__ float red[8];

    int tid = threadIdx.x;
    int bxid = blockIdx.x;
    int jt = bxid & (NJT - 1);
    int ks = bxid >> 4;
    int lane = tid & 31, w = tid >> 5;
    int g = lane >> 2, tg = lane & 3;
    int wm = (w & 3) * 32, wn = (w >> 2) * 32;

    // Pre-split this CTA's W_hh slice: rows jt*64..+63, k = ks*128..+127
    {
        int n = tid >> 2;
        int q = tid & 3;                  // word quarter: 16 words = 32 floats
        const float* src = Whh + (size_t)(jt * 64 + n) * HH + ks * 128 + q * 32;
        unsigned hw[16], lw[16];
        #pragma unroll
        for (int i = 0; i < 8; i++) {
            float4 v = *(const float4*)(src + 4 * i);
            split_pair(v.x, v.y, hw[2 * i], lw[2 * i]);
            split_pair(v.z, v.w, hw[2 * i + 1], lw[2 * i + 1]);
        }
        uint4* dh = (uint4*)&Bsh[n * AW + q * 16];
        uint4* dl = (uint4*)&Bsl[n * AW + q * 16];
        #pragma unroll
        for (int i = 0; i < 4; i++) {
            dh[i] = make_uint4(hw[4 * i], hw[4 * i + 1], hw[4 * i + 2], hw[4 * i + 3]);
            dl[i] = make_uint4(lw[4 * i], lw[4 * i + 1], lw[4 * i + 2], lw[4 * i + 3]);
        }
    }
    __syncthreads();

    int r = tid >> 1, half = tid & 1;
    unsigned gen = 0;

    for (int t = 0; t < TT; t++) {
        // ---- phase 1: stage pre-split h slice (no conversion) ----
        {
            const uint4* sh = (const uint4*)&g_hhi[r * (HH / 2) + ks * 64 + half * 32];
            const uint4* sl = (const uint4*)&g_hlo[r * (HH / 2) + ks * 64 + half * 32];
            uint4* dh = (uint4*)&Ash[r * AW + half * 32];
            uint4* dl = (uint4*)&Asl[r * AW + half * 32];
            #pragma unroll
            for (int i = 0; i < 8; i++) { dh[i] = sh[i]; dl[i] = sl[i]; }
        }
        __syncthreads();

        float acc[2][4][4];
        #pragma unroll
        for (int i = 0; i < 2; i++)
            #pragma unroll
            for (int j = 0; j < 4; j++)
                #pragma unroll
                for (int k = 0; k < 4; k++) acc[i][j][k] = 0.0f;

        #pragma unroll
        for (int ki = 0; ki < 8; ki++) {
            int k0 = ki * 8;
            unsigned ah[2][4], al[2][4], bh[4][2], bl[4][2];
            #pragma unroll
            for (int mi = 0; mi < 2; mi++) {
                int base = (wm + 16 * mi + g) * AW + k0 + tg;
                ah[mi][0] = Ash[base];          ah[mi][1] = Ash[base + 8 * AW];
                ah[mi][2] = Ash[base + 4];      ah[mi][3] = Ash[base + 8 * AW + 4];
                al[mi][0] = Asl[base];          al[mi][1] = Asl[base + 8 * AW];
                al[mi][2] = Asl[base + 4];      al[mi][3] = Asl[base + 8 * AW + 4];
            }
            #pragma unroll
            for (int ni = 0; ni < 4; ni++) {
                int base = (wn + 8 * ni + g) * AW + k0 + tg;
                bh[ni][0] = Bsh[base]; bh[ni][1] = Bsh[base + 4];
                bl[ni][0] = Bsl[base]; bl[ni][1] = Bsl[base + 4];
            }
            #pragma unroll
            for (int mi = 0; mi < 2; mi++)
                #pragma unroll
                for (int ni = 0; ni < 4; ni++) {
                    MMA_BF16(acc[mi][ni], ah[mi], bh[ni]);
                    MMA_BF16(acc[mi][ni], ah[mi], bl[ni]);
                    MMA_BF16(acc[mi][ni], al[mi], bh[ni]);
                }
        }

        {
            float* pbase = g_part[ks];
            #pragma unroll
            for (int mi = 0; mi < 2; mi++)
                #pragma unroll
                for (int ni = 0; ni < 4; ni++) {
                    int row = wm + 16 * mi + g;
                    int col = jt * 64 + wn + 8 * ni + 2 * tg;
                    *(float2*)(pbase + row * HH + col) =
                        make_float2(acc[mi][ni][0], acc[mi][ni][1]);
                    *(float2*)(pbase + (row + 8) * HH + col) =
                        make_float2(acc[mi][ni][2], acc[mi][ni][3]);
                }
        }
        gsync(++gen, bxid, tid);

        // ---- phase 2: reduce + tanh + write pre-split h + head dot ----
        {
            int b = bxid;
            int j = tid * 4;
            float4 s = *(const float4*)(g_xp + ((size_t)t * BB + b) * HH + j);
            #pragma unroll
            for (int p = 0; p < NKS; p++) {
                float4 v = *(const float4*)(g_part[p] + b * HH + j);
                s.x += v.x; s.y += v.y; s.z += v.z; s.w += v.w;
            }
            float h0 = tanhf(s.x), h1 = tanhf(s.y), h2 = tanhf(s.z), h3 = tanhf(s.w);

            unsigned w01h, w01l, w23h, w23l;
            split_pair(h0, h1, w01h, w01l);
            split_pair(h2, h3, w23h, w23l);
            *(uint2*)&g_hhi[b * (HH / 2) + tid * 2] = make_uint2(w01h, w23h);
            *(uint2*)&g_hlo[b * (HH / 2) + tid * 2] = make_uint2(w01l, w23l);

            float4 wv = *(const float4*)(Wfc + j);
            float dot = h0 * wv.x + h1 * wv.y + h2 * wv.z + h3 * wv.w;
            #pragma unroll
            for (int o = 16; o > 0; o >>= 1)
                dot += __shfl_down_sync(0xFFFFFFFFu, dot, o);
            if (lane == 0) red[w] = dot;
            __syncthreads();
            if (tid == 0) {
                float sum = red[0] + red[1] + red[2] + red[3]
                          + red[4] + red[5] + red[6] + red[7];
                out[t * BB + b] = sum + bfc[0];
            }
        }
        gsync(++gen, bxid, tid);
    }
}

// ---------------------------------------------------------------------------
extern "C" void kernel_launch(void* const* d_in, const int* in_sizes, int n_in,
                              void* d_out, int out_size) {
    const float* x   = (const float*)d_in[0];
    const float* Wih = (const float*)d_in[1];
    const float* Whh = (const float*)d_in[2];
    const float* bih = (const float*)d_in[3];
    const float* bhh = (const float*)d_in[4];
    const float* Wfc = (const float*)d_in[5];
    const float* bfc = (const float*)d_in[6];
    float* out = (float*)d_out;

    static int configured = 0;
    if (!configured) {
        cudaFuncSetAttribute(rnn_persistent, cudaFuncAttributeMaxDynamicSharedMemorySize,
                             (64 * AW * 2 + 128 * AW * 2) * 4);
        configured = 1;
    }

    init_kernel<<<512, 256>>>();
    xp_mma<<<dim3(8, 256), 256>>>(x, Wih, bih, bhh);
    rnn_persistent<<<GRID_P, 256, (64 * AW * 2 + 128 * AW * 2) * 4>>>(Whh, Wfc, bfc, out);
}

// round 10
// speedup vs baseline: 1.7028x; 1.2338x over previous
#include <cuda_runtime.h>
#include <cuda_bf16.h>
#include <cstdint>

#define TT 256
#define BB 128
#define II 512
#define HH 1024
#define NJT 16
#define NKS 8
#define GRID_P (NJT * NKS)   // 128 persistent CTAs
#define XW 20                // xp kernel smem row stride (words)
#define RS 36                // persistent kernel smem row stride (words) -> conflict-free frags

// smem word offsets (persistent kernel)
#define W_A1 0
#define W_A2 4608            // 128*36
#define W_B1 9216
#define W_B2 11520           // + 64*36
#define W_RED 13824
#define SM_WORDS (13824 + 16)

// ---------------- scratch ---------------------------------------------------
__device__ float g_xp[(size_t)TT * BB * HH];
__device__ unsigned g_h1w[BB * HH / 4];   // h word1: 4 int8 per word (scale 127)
__device__ unsigned g_h2w[BB * HH / 4];   // h word2: residual int8 (scale 127*254)
__device__ float g_part[NKS][BB * HH];
__device__ unsigned g_flags[GRID_P * 32]; // one flag per 128B line
__device__ unsigned g_gen;

// ---------------- bf16 split helpers (xp kernel) ----------------------------
__device__ __forceinline__ float bhi(float x) {
    unsigned u = __float_as_uint(x);
    u = (u + 0x7FFFu + ((u >> 16) & 1u)) & 0xFFFF0000u;
    return __uint_as_float(u);
}
__device__ __forceinline__ void split_pair(float e, float o, unsigned &whi, unsigned &wlo) {
    float eh = bhi(e), oh = bhi(o);
    whi = (__float_as_uint(eh) >> 16) | (__float_as_uint(oh) & 0xFFFF0000u);
    float el = e - eh, ol = o - oh;
    asm("cvt.rn.bf16x2.f32 %0, %1, %2;" : "=r"(wlo) : "f"(ol), "f"(el));
}

#define MMA_BF16(d, a, b)                                                       \
    asm volatile(                                                               \
        "mma.sync.aligned.m16n8k16.row.col.f32.bf16.bf16.f32 "                  \
        "{%0,%1,%2,%3},{%4,%5,%6,%7},{%8,%9},{%0,%1,%2,%3};\n"                  \
        : "+f"((d)[0]), "+f"((d)[1]), "+f"((d)[2]), "+f"((d)[3])                \
        : "r"((a)[0]), "r"((a)[1]), "r"((a)[2]), "r"((a)[3]),                   \
          "r"((b)[0]), "r"((b)[1]))

#define MMA_S8(d, a, b)                                                         \
    asm volatile(                                                               \
        "mma.sync.aligned.m16n8k32.row.col.s32.s8.s8.s32 "                      \
        "{%0,%1,%2,%3},{%4,%5,%6,%7},{%8,%9},{%0,%1,%2,%3};\n"                  \
        : "+r"((d)[0]), "+r"((d)[1]), "+r"((d)[2]), "+r"((d)[3])                \
        : "r"((a)[0]), "r"((a)[1]), "r"((a)[2]), "r"((a)[3]),                   \
          "r"((b)[0]), "r"((b)[1]))

__device__ __forceinline__ unsigned pack4(int a, int b, int c, int d) {
    return (unsigned)(a & 0xFF) | ((unsigned)(b & 0xFF) << 8) |
           ((unsigned)(c & 0xFF) << 16) | ((unsigned)(d & 0xFF) << 24);
}

// ---------------- flag barrier (single hop: every CTA polls all flags) ------
__device__ __forceinline__ unsigned ld_acq(const unsigned* p) {
    unsigned v; asm volatile("ld.acquire.gpu.global.u32 %0, [%1];" : "=r"(v) : "l"(p)); return v;
}
__device__ __forceinline__ void st_rel(unsigned* p, unsigned v) {
    asm volatile("st.release.gpu.global.u32 [%0], %1;" :: "l"(p), "r"(v));
}
__device__ __forceinline__ void gsync(unsigned gen, int bxid, int tid) {
    __syncthreads();
    if (tid == 0) st_rel(&g_flags[bxid * 32], gen);
    if (tid < GRID_P) { while (ld_acq(&g_flags[tid * 32]) < gen) {} }
    __syncthreads();
}

// ---------------- init ------------------------------------------------------
__global__ void init_kernel() {
    int i = blockIdx.x * blockDim.x + threadIdx.x;
    if (i < BB * HH / 4) { g_h1w[i] = 0u; g_h2w[i] = 0u; }
    if (i < GRID_P * 32) g_flags[i] = 0u;
    if (i == 0) g_gen = 0u;
}

// ---------------------------------------------------------------------------
// xp = x @ W_ih^T + b_ih + b_hh via legacy bf16x3 mma (unchanged).
// ---------------------------------------------------------------------------
__global__ __launch_bounds__(256) void xp_mma(const float* __restrict__ x,
                                              const float* __restrict__ Wih,
                                              const float* __restrict__ bih,
                                              const float* __restrict__ bhh) {
    __shared__ unsigned Ash[128 * XW], Asl[128 * XW];
    __shared__ unsigned Bsh[128 * XW], Bsl[128 * XW];

    int tid = threadIdx.x;
    int lane = tid & 31, w = tid >> 5;
    int g = lane >> 2, tg = lane & 3;
    int wm = (w & 1) * 64, wn = (w >> 1) * 32;
    int bn = blockIdx.x, bm = blockIdx.y;

    float acc[4][4][4];
    #pragma unroll
    for (int i = 0; i < 4; i++)
        #pragma unroll
        for (int j = 0; j < 4; j++)
            #pragma unroll
            for (int k = 0; k < 4; k++) acc[i][j][k] = 0.0f;

    int r = tid >> 1, half = tid & 1;
    const float* ax = x   + (size_t)(bm * 128 + r) * II + half * 16;
    const float* bw = Wih + (size_t)(bn * 128 + r) * II + half * 16;

    for (int kb = 0; kb < II; kb += 32) {
        unsigned hw[8], lw[8];
        #pragma unroll
        for (int i = 0; i < 4; i++) {
            float4 v = *(const float4*)(ax + kb + 4 * i);
            split_pair(v.x, v.y, hw[2 * i], lw[2 * i]);
            split_pair(v.z, v.w, hw[2 * i + 1], lw[2 * i + 1]);
        }
        {
            uint4* dh = (uint4*)&Ash[r * XW + half * 8];
            uint4* dl = (uint4*)&Asl[r * XW + half * 8];
            dh[0] = make_uint4(hw[0], hw[1], hw[2], hw[3]);
            dh[1] = make_uint4(hw[4], hw[5], hw[6], hw[7]);
            dl[0] = make_uint4(lw[0], lw[1], lw[2], lw[3]);
            dl[1] = make_uint4(lw[4], lw[5], lw[6], lw[7]);
        }
        #pragma unroll
        for (int i = 0; i < 4; i++) {
            float4 v = *(const float4*)(bw + kb + 4 * i);
            split_pair(v.x, v.y, hw[2 * i], lw[2 * i]);
            split_pair(v.z, v.w, hw[2 * i + 1], lw[2 * i + 1]);
        }
        {
            uint4* dh = (uint4*)&Bsh[r * XW + half * 8];
            uint4* dl = (uint4*)&Bsl[r * XW + half * 8];
            dh[0] = make_uint4(hw[0], hw[1], hw[2], hw[3]);
            dh[1] = make_uint4(hw[4], hw[5], hw[6], hw[7]);
            dl[0] = make_uint4(lw[0], lw[1], lw[2], lw[3]);
            dl[1] = make_uint4(lw[4], lw[5], lw[6], lw[7]);
        }
        __syncthreads();

        #pragma unroll
        for (int ki = 0; ki < 2; ki++) {
            int k0 = ki * 8;
            unsigned ah[4][4], al[4][4], bh[4][2], bl[4][2];
            #pragma unroll
            for (int mi = 0; mi < 4; mi++) {
                int base = (wm + 16 * mi + g) * XW + k0 + tg;
                ah[mi][0] = Ash[base];          ah[mi][1] = Ash[base + 8 * XW];
                ah[mi][2] = Ash[base + 4];      ah[mi][3] = Ash[base + 8 * XW + 4];
                al[mi][0] = Asl[base];          al[mi][1] = Asl[base + 8 * XW];
                al[mi][2] = Asl[base + 4];      al[mi][3] = Asl[base + 8 * XW + 4];
            }
            #pragma unroll
            for (int ni = 0; ni < 4; ni++) {
                int base = (wn + 8 * ni + g) * XW + k0 + tg;
                bh[ni][0] = Bsh[base]; bh[ni][1] = Bsh[base + 4];
                bl[ni][0] = Bsl[base]; bl[ni][1] = Bsl[base + 4];
            }
            #pragma unroll
            for (int mi = 0; mi < 4; mi++)
                #pragma unroll
                for (int ni = 0; ni < 4; ni++) {
                    MMA_BF16(acc[mi][ni], ah[mi], bh[ni]);
                    MMA_BF16(acc[mi][ni], ah[mi], bl[ni]);
                    MMA_BF16(acc[mi][ni], al[mi], bh[ni]);
                }
        }
        __syncthreads();
    }

    #pragma unroll
    for (int mi = 0; mi < 4; mi++)
        #pragma unroll
        for (int ni = 0; ni < 4; ni++) {
            int m = bm * 128 + wm + 16 * mi + g;
            int n = bn * 128 + wn + 8 * ni + 2 * tg;
            float b0 = bih[n] + bhh[n];
            float b1 = bih[n + 1] + bhh[n + 1];
            *(float2*)(g_xp + (size_t)m * HH + n) =
                make_float2(acc[mi][ni][0] + b0, acc[mi][ni][1] + b1);
            *(float2*)(g_xp + (size_t)(m + 8) * HH + n) =
                make_float2(acc[mi][ni][2] + b0, acc[mi][ni][3] + b1);
        }
}

// ---------------------------------------------------------------------------
// Persistent recurrence: 128 CTAs = 16 jt x 8 ks, 256 threads, int8 dual-word
// split mma (s8 m16n8k32). W split once per CTA with its own pow-free scale.
// ---------------------------------------------------------------------------
__global__ __launch_bounds__(256, 1) void rnn_persistent(const float* __restrict__ Whh,
                                                         const float* __restrict__ Wfc,
                                                         const float* __restrict__ bfc,
                                                         float* __restrict__ out) {
    extern __shared__ unsigned smw[];
    unsigned* A1 = smw + W_A1;
    unsigned* A2 = smw + W_A2;
    unsigned* B1 = smw + W_B1;
    unsigned* B2 = smw + W_B2;
    float* redf = (float*)(smw + W_RED);

    int tid = threadIdx.x;
    int bxid = blockIdx.x;
    int jt = bxid & (NJT - 1);
    int ks = bxid >> 4;
    int lane = tid & 31, w = tid >> 5;
    int g = lane >> 2, tg = lane & 3;
    int wm = (w & 3) * 32, wn = (w >> 2) * 32;

    // ---- prologue: per-CTA W_hh slice -> int8 dual-word, with CTA scale ----
    float c1, c2;
    {
        int n = tid >> 2;            // 0..63 (row jt*64+n)
        int q = tid & 3;             // k quarter (32 floats)
        const float* src = Whh + (size_t)(jt * 64 + n) * HH + ks * 128 + q * 32;
        float wv[32];
        #pragma unroll
        for (int c = 0; c < 8; c++) {
            float4 v = *(const float4*)(src + 4 * c);
            wv[4 * c] = v.x; wv[4 * c + 1] = v.y; wv[4 * c + 2] = v.z; wv[4 * c + 3] = v.w;
        }
        float m = 0.0f;
        #pragma unroll
        for (int i = 0; i < 32; i++) m = fmaxf(m, fabsf(wv[i]));
        #pragma unroll
        for (int o = 16; o > 0; o >>= 1)
            m = fmaxf(m, __shfl_xor_sync(0xFFFFFFFFu, m, o));
        if (lane == 0) redf[w] = m;
        __syncthreads();
        if (tid == 0) {
            float mm = redf[0];
            #pragma unroll
            for (int i = 1; i < 8; i++) mm = fmaxf(mm, redf[i]);
            redf[8] = mm;
        }
        __syncthreads();
        float absmax = redf[8];
        float Sw = 127.0f / absmax;
        c1 = 1.0f / (Sw * 127.0f);
        c2 = c1 * (1.0f / 254.0f);

        unsigned w1[8], w2[8];
        #pragma unroll
        for (int c = 0; c < 8; c++) {
            int i1[4], i2[4];
            #pragma unroll
            for (int e = 0; e < 4; e++) {
                float s = wv[4 * c + e] * Sw;
                i1[e] = (int)rintf(s);
                float r = s - (float)i1[e];
                i2[e] = (int)rintf(r * 254.0f);
            }
            w1[c] = pack4(i1[0], i1[1], i1[2], i1[3]);
            w2[c] = pack4(i2[0], i2[1], i2[2], i2[3]);
        }
        uint4* d1 = (uint4*)&B1[n * RS + q * 8];
        uint4* d2 = (uint4*)&B2[n * RS + q * 8];
        d1[0] = make_uint4(w1[0], w1[1], w1[2], w1[3]);
        d1[1] = make_uint4(w1[4], w1[5], w1[6], w1[7]);
        d2[0] = make_uint4(w2[0], w2[1], w2[2], w2[3]);
        d2[1] = make_uint4(w2[4], w2[5], w2[6], w2[7]);
    }
    __syncthreads();

    int r = tid >> 1, half = tid & 1;
    unsigned gen = 0;

    for (int t = 0; t < TT; t++) {
        // ---- stage packed int8 h slice (pure copy, 8 LDG.128 + 8 STS.128) ----
        {
            const uint4* s1 = (const uint4*)&g_h1w[r * 256 + ks * 32 + half * 16];
            const uint4* s2 = (const uint4*)&g_h2w[r * 256 + ks * 32 + half * 16];
            uint4* d1 = (uint4*)&A1[r * RS + half * 16];
            uint4* d2 = (uint4*)&A2[r * RS + half * 16];
            #pragma unroll
            for (int i = 0; i < 4; i++) { d1[i] = s1[i]; d2[i] = s2[i]; }
        }
        __syncthreads();

        int acc1[2][4][4], acc2[2][4][4];
        #pragma unroll
        for (int i = 0; i < 2; i++)
            #pragma unroll
            for (int j = 0; j < 4; j++)
                #pragma unroll
                for (int k = 0; k < 4; k++) { acc1[i][j][k] = 0; acc2[i][j][k] = 0; }

        #pragma unroll
        for (int ki = 0; ki < 4; ki++) {
            int kb = ki * 8 + tg;
            unsigned a1f[2][4], a2f[2][4], b1f[4][2], b2f[4][2];
            #pragma unroll
            for (int mi = 0; mi < 2; mi++) {
                int base = (wm + 16 * mi + g) * RS + kb;
                a1f[mi][0] = A1[base];          a1f[mi][1] = A1[base + 8 * RS];
                a1f[mi][2] = A1[base + 4];      a1f[mi][3] = A1[base + 8 * RS + 4];
                a2f[mi][0] = A2[base];          a2f[mi][1] = A2[base + 8 * RS];
                a2f[mi][2] = A2[base + 4];      a2f[mi][3] = A2[base + 8 * RS + 4];
            }
            #pragma unroll
            for (int ni = 0; ni < 4; ni++) {
                int base = (wn + 8 * ni + g) * RS + kb;
                b1f[ni][0] = B1[base]; b1f[ni][1] = B1[base + 4];
                b2f[ni][0] = B2[base]; b2f[ni][1] = B2[base + 4];
            }
            #pragma unroll
            for (int mi = 0; mi < 2; mi++)
                #pragma unroll
                for (int ni = 0; ni < 4; ni++) {
                    MMA_S8(acc1[mi][ni], a1f[mi], b1f[ni]);
                    MMA_S8(acc2[mi][ni], a1f[mi], b2f[ni]);
                    MMA_S8(acc2[mi][ni], a2f[mi], b1f[ni]);
                }
        }

        // ---- write fp32 partials ----
        {
            float* pbase = g_part[ks];
            #pragma unroll
            for (int mi = 0; mi < 2; mi++)
                #pragma unroll
                for (int ni = 0; ni < 4; ni++) {
                    int row = wm + 16 * mi + g;
                    int col = jt * 64 + wn + 8 * ni + 2 * tg;
                    float v0 = c1 * (float)acc1[mi][ni][0] + c2 * (float)acc2[mi][ni][0];
                    float v1 = c1 * (float)acc1[mi][ni][1] + c2 * (float)acc2[mi][ni][1];
                    float v2 = c1 * (float)acc1[mi][ni][2] + c2 * (float)acc2[mi][ni][2];
                    float v3 = c1 * (float)acc1[mi][ni][3] + c2 * (float)acc2[mi][ni][3];
                    *(float2*)(pbase + (size_t)row * HH + col) = make_float2(v0, v1);
                    *(float2*)(pbase + (size_t)(row + 8) * HH + col) = make_float2(v2, v3);
                }
        }
        gsync(++gen, bxid, tid);

        // ---- phase 2: reduce + tanh + quantize h + head dot ----
        {
            int b = bxid;
            int j = tid * 4;
            float4 s = *(const float4*)(g_xp + ((size_t)t * BB + b) * HH + j);
            #pragma unroll
            for (int p = 0; p < NKS; p++) {
                float4 v = *(const float4*)(g_part[p] + (size_t)b * HH + j);
                s.x += v.x; s.y += v.y; s.z += v.z; s.w += v.w;
            }
            float h0 = tanhf(s.x), h1 = tanhf(s.y), h2 = tanhf(s.z), h3 = tanhf(s.w);

            int i1[4], i2[4];
            float hv[4] = {h0, h1, h2, h3};
            #pragma unroll
            for (int e = 0; e < 4; e++) {
                float sc = hv[e] * 127.0f;
                i1[e] = (int)rintf(sc);
                float rr = sc - (float)i1[e];
                i2[e] = (int)rintf(rr * 254.0f);
            }
            g_h1w[b * 256 + tid] = pack4(i1[0], i1[1], i1[2], i1[3]);
            g_h2w[b * 256 + tid] = pack4(i2[0], i2[1], i2[2], i2[3]);

            float4 wv = *(const float4*)(Wfc + j);
            float dot = h0 * wv.x + h1 * wv.y + h2 * wv.z + h3 * wv.w;
            #pragma unroll
            for (int o = 16; o > 0; o >>= 1)
                dot += __shfl_down_sync(0xFFFFFFFFu, dot, o);
            if (lane == 0) redf[w] = dot;
            __syncthreads();
            if (tid == 0) {
                float sum = redf[0] + redf[1] + redf[2] + redf[3]
                          + redf[4] + redf[5] + redf[6] + redf[7];
                out[t * BB + b] = sum + bfc[0];
            }
        }
        gsync(++gen, bxid, tid);
    }
}

// ---------------------------------------------------------------------------
extern "C" void kernel_launch(void* const* d_in, const int* in_sizes, int n_in,
                              void* d_out, int out_size) {
    const float* x   = (const float*)d_in[0];
    const float* Wih = (const float*)d_in[1];
    const float* Whh = (const float*)d_in[2];
    const float* bih = (const float*)d_in[3];
    const float* bhh = (const float*)d_in[4];
    const float* Wfc = (const float*)d_in[5];
    const float* bfc = (const float*)d_in[6];
    float* out = (float*)d_out;

    static int configured = 0;
    if (!configured) {
        cudaFuncSetAttribute(rnn_persistent, cudaFuncAttributeMaxDynamicSharedMemorySize,
                             SM_WORDS * 4);
        configured = 1;
    }

    init_kernel<<<512, 256>>>();
    xp_mma<<<dim3(8, 256), 256>>>(x, Wih, bih, bhh);
    rnn_persistent<<<GRID_P, 256, SM_WORDS * 4>>>(Whh, Wfc, bfc, out);
}